// round 1
// baseline (speedup 1.0000x reference)
#include <cuda_runtime.h>
#include <math.h>

// Problem constants (fixed by the dataset)
#define NN 100000
#define EE 1600000
#define FF 128
#define DD 64
#define GG 512
#define SCAN_BLK 512
#define NBLK ((NN + SCAN_BLK - 1) / SCAN_BLK)   // 196

// ---------------- device scratch (static globals; no allocation) -------------
__device__ __align__(16) float g_u[NN * DD];   // u = A@W1 (layer input transformed)
__device__ __align__(16) float g_t[NN * DD];   // t = relu(u + agg + b1)
__device__ __align__(16) float g_r[NN * DD];   // r = relu(t@W2 + b2)  (pre-BN)
__device__ __align__(16) float g_h[NN * DD];   // h = BN(r)  (layer-0 output)
__device__ int   g_deg[NN];
__device__ int   g_off[NN];
__device__ int   g_cur[NN];
__device__ uint2 g_csr[EE];                    // {src, bitcast(weight)}
__device__ int   g_bsum[NBLK];
__device__ float g_colsum[2 * DD];
__device__ float g_colsq[2 * DD];
__device__ __align__(16) float g_pool[GG * 2 * DD];  // [G][128]: p0 cols 0..63, p1 cols 64..127
__device__ int   g_is64_ei;
__device__ int   g_is64_b;

// ---------------- helpers ----------------------------------------------------
__device__ __forceinline__ int ld_idx(const void* p, int i, int is64) {
    return is64 ? (int)((const long long*)p)[i] : ((const int*)p)[i];
}

// ---------------- dtype sniffing (int64 vs int32 index tensors) --------------
// If data is int64 (values < 2^31, nonneg), every odd 32-bit word is 0.
// Probe positions chosen to stay inside the int32-sized buffer too.
__global__ void detect_kernel(const void* ei, const void* batch) {
    if (threadIdx.x == 0 && blockIdx.x == 0) {
        const int* p = (const int*)ei;
        int nz = 0;
        #pragma unroll
        for (int k = 0; k < 16; k++) {
            int i = 1000 + k * 9973;          // i < EE; odd word index 2i+1 < 2*EE
            if (p[2 * i + 1] != 0) nz++;
        }
        g_is64_ei = (nz == 0) ? 1 : 0;
        const int* q = (const int*)batch;
        int nz2 = 0;
        #pragma unroll
        for (int k = 0; k < 16; k++) {
            int i = 40000 + k * 601;          // middle of sorted batch: values ~200-260, nonzero
            if (q[2 * i + 1] != 0) nz2++;     // 2i+1 < NN so safe if int32
        }
        g_is64_b = (nz2 == 0) ? 1 : 0;
    }
}

// ---------------- init -------------------------------------------------------
__global__ void zero_kernel() {
    int i = blockIdx.x * blockDim.x + threadIdx.x;
    if (i < NN) g_deg[i] = 0;
    if (i < 2 * DD) { g_colsum[i] = 0.f; g_colsq[i] = 0.f; }
    if (i < GG * 2 * DD) g_pool[i] = 0.f;
}

// ---------------- CSR build --------------------------------------------------
__global__ void hist_kernel(const void* ei) {
    int e = blockIdx.x * blockDim.x + threadIdx.x;
    if (e >= EE) return;
    int is64 = g_is64_ei;
    int d = ld_idx(ei, EE + e, is64);
    atomicAdd(&g_deg[d], 1);
}

__global__ void scanA_kernel() {
    __shared__ int s[SCAN_BLK];
    int t = threadIdx.x;
    int i = blockIdx.x * SCAN_BLK + t;
    int v = (i < NN) ? g_deg[i] : 0;
    s[t] = v;
    __syncthreads();
    for (int off = 1; off < SCAN_BLK; off <<= 1) {
        int add = (t >= off) ? s[t - off] : 0;
        __syncthreads();
        s[t] += add;
        __syncthreads();
    }
    if (i < NN) g_off[i] = s[t] - v;            // exclusive (local)
    if (t == SCAN_BLK - 1) g_bsum[blockIdx.x] = s[SCAN_BLK - 1];
}

__global__ void scanB_kernel() {
    if (threadIdx.x == 0 && blockIdx.x == 0) {
        int run = 0;
        for (int b = 0; b < NBLK; b++) { int x = g_bsum[b]; g_bsum[b] = run; run += x; }
    }
}

__global__ void scanC_kernel() {
    int i = blockIdx.x * blockDim.x + threadIdx.x;
    if (i >= NN) return;
    int o = g_off[i] + g_bsum[i >> 9];
    g_off[i] = o;
    g_cur[i] = o;
}

__global__ void fill_kernel(const void* ei, const float* __restrict__ ew) {
    int e = blockIdx.x * blockDim.x + threadIdx.x;
    if (e >= EE) return;
    int is64 = g_is64_ei;
    int s = ld_idx(ei, e, is64);
    int d = ld_idx(ei, EE + e, is64);
    int pos = atomicAdd(&g_cur[d], 1);
    g_csr[pos] = make_uint2((unsigned)s, __float_as_uint(ew[e]));
}

// ---------------- GEMM: C[n][c] = act(sum_k A[n][k] W[k][c] + bias[c]) -------
// Block: 64 rows x 64 cols, 256 threads, each 4 rows x 4 cols. K chunked by 64.
template <int K, bool RELU>
__global__ void __launch_bounds__(256) gemm_kernel(
    const float* __restrict__ A, const float* __restrict__ W,
    const float* __restrict__ bias, float* __restrict__ C, int nrows)
{
    __shared__ float As[64 * 64];
    __shared__ float Ws[64 * 64];
    int t  = threadIdx.x;
    int cg = t & 15;     // cols 4*cg .. 4*cg+3
    int ng = t >> 4;     // rows 4*ng .. 4*ng+3
    int n0 = blockIdx.x * 64;

    float acc[4][4];
    #pragma unroll
    for (int i = 0; i < 4; i++)
        #pragma unroll
        for (int j = 0; j < 4; j++) acc[i][j] = 0.f;

    for (int kc = 0; kc < K; kc += 64) {
        #pragma unroll
        for (int j = 0; j < 4; j++) {
            int idx = t + j * 256;           // float4 index 0..1023
            int r   = idx >> 4;
            int k4  = idx & 15;
            float4 v = make_float4(0.f, 0.f, 0.f, 0.f);
            int row = n0 + r;
            if (row < nrows)
                v = *(const float4*)&A[(size_t)row * K + kc + 4 * k4];
            *(float4*)&As[r * 64 + 4 * k4] = v;
            *(float4*)&Ws[r * 64 + 4 * k4] =
                *(const float4*)&W[(size_t)(kc + r) * DD + 4 * k4];
        }
        __syncthreads();
        #pragma unroll
        for (int k = 0; k < 64; k++) {
            float4 w4 = *(float4*)&Ws[k * 64 + 4 * cg];
            #pragma unroll
            for (int i = 0; i < 4; i++) {
                float a = As[(4 * ng + i) * 64 + k];
                acc[i][0] += a * w4.x;
                acc[i][1] += a * w4.y;
                acc[i][2] += a * w4.z;
                acc[i][3] += a * w4.w;
            }
        }
        __syncthreads();
    }

    float4 b4 = bias ? *(const float4*)&bias[4 * cg] : make_float4(0.f, 0.f, 0.f, 0.f);
    #pragma unroll
    for (int i = 0; i < 4; i++) {
        int row = n0 + 4 * ng + i;
        if (row >= nrows) continue;
        float4 o;
        o.x = acc[i][0] + b4.x; o.y = acc[i][1] + b4.y;
        o.z = acc[i][2] + b4.z; o.w = acc[i][3] + b4.w;
        if (RELU) {
            o.x = fmaxf(o.x, 0.f); o.y = fmaxf(o.y, 0.f);
            o.z = fmaxf(o.z, 0.f); o.w = fmaxf(o.w, 0.f);
        }
        *(float4*)&C[(size_t)row * DD + 4 * cg] = o;
    }
}

// ---------------- aggregation: one warp per node, CSR gather, no atomics -----
// t[node] = relu(u[node] + sum_{e in csr[node]} w_e * u[src_e] + bias)
__global__ void __launch_bounds__(256) agg_kernel(
    const float* __restrict__ U, const float* __restrict__ bias,
    float* __restrict__ T)
{
    int w = (blockIdx.x * blockDim.x + threadIdx.x) >> 5;
    int lane = threadIdx.x & 31;
    if (w >= NN) return;
    int s  = g_off[w];
    int dg = g_deg[w];
    float a0 = 0.f, a1 = 0.f;
    int e = 0;
    for (; e + 4 <= dg; e += 4) {
        uint2 c0 = g_csr[s + e + 0];
        uint2 c1 = g_csr[s + e + 1];
        uint2 c2 = g_csr[s + e + 2];
        uint2 c3 = g_csr[s + e + 3];
        float2 v0 = *(const float2*)(U + (size_t)c0.x * DD + 2 * lane);
        float2 v1 = *(const float2*)(U + (size_t)c1.x * DD + 2 * lane);
        float2 v2 = *(const float2*)(U + (size_t)c2.x * DD + 2 * lane);
        float2 v3 = *(const float2*)(U + (size_t)c3.x * DD + 2 * lane);
        float w0 = __uint_as_float(c0.y), w1 = __uint_as_float(c1.y);
        float w2 = __uint_as_float(c2.y), w3 = __uint_as_float(c3.y);
        a0 += w0 * v0.x; a1 += w0 * v0.y;
        a0 += w1 * v1.x; a1 += w1 * v1.y;
        a0 += w2 * v2.x; a1 += w2 * v2.y;
        a0 += w3 * v3.x; a1 += w3 * v3.y;
    }
    for (; e < dg; e++) {
        uint2 c = g_csr[s + e];
        float2 v = *(const float2*)(U + (size_t)c.x * DD + 2 * lane);
        float ww = __uint_as_float(c.y);
        a0 += ww * v.x; a1 += ww * v.y;
    }
    float2 u2 = *(const float2*)(U + (size_t)w * DD + 2 * lane);
    float b0 = bias[2 * lane], b1 = bias[2 * lane + 1];
    float2 o;
    o.x = fmaxf(u2.x + a0 + b0, 0.f);
    o.y = fmaxf(u2.y + a1 + b1, 0.f);
    *(float2*)(T + (size_t)w * DD + 2 * lane) = o;
}

// ---------------- column stats (sum, sumsq) over N rows ----------------------
__global__ void colstats_kernel(const float* __restrict__ R,
                                float* __restrict__ csum, float* __restrict__ csq)
{
    __shared__ float ss[256], sq[256];
    int t = threadIdx.x;
    int c = t & 63;
    int p = t >> 6;
    int chunk = (NN + gridDim.x - 1) / gridDim.x;
    int n0 = blockIdx.x * chunk;
    int n1 = min(n0 + chunk, NN);
    float s = 0.f, q = 0.f;
    for (int n = n0 + p; n < n1; n += 4) {
        float v = R[(size_t)n * DD + c];
        s += v; q += v * v;
    }
    ss[t] = s; sq[t] = q;
    __syncthreads();
    if (p == 0) {
        float S = ss[c] + ss[c + 64] + ss[c + 128] + ss[c + 192];
        float Q = sq[c] + sq[c + 64] + sq[c + 128] + sq[c + 192];
        atomicAdd(&csum[c], S);
        atomicAdd(&csq[c], Q);
    }
}

// ---------------- BN normalize + global_add_pool (batch is sorted) -----------
__global__ void bnpool_kernel(const float* __restrict__ R, const void* batch,
                              const float* __restrict__ gamma, const float* __restrict__ beta,
                              const float* __restrict__ csum, const float* __restrict__ csq,
                              float* __restrict__ H, int pooloff)
{
    const int NCH = 128;
    int c  = threadIdx.x;      // 64 threads, one per column
    int n0 = blockIdx.x * NCH;
    int is64 = g_is64_b;
    float mean = csum[c] * (1.f / NN);
    float var  = csq[c] * (1.f / NN) - mean * mean;
    float sc = gamma[c] * rsqrtf(var + 1e-5f);
    float sh = beta[c] - mean * sc;
    float run = 0.f;
    int curb = -1;
    int n1 = min(n0 + NCH, NN);
    for (int n = n0; n < n1; n++) {
        int b = ld_idx(batch, n, is64);
        float h = R[(size_t)n * DD + c] * sc + sh;
        if (H) H[(size_t)n * DD + c] = h;
        if (b != curb) {
            if (curb >= 0) atomicAdd(&g_pool[curb * 128 + pooloff + c], run);
            run = 0.f;
            curb = b;
        }
        run += h;
    }
    if (curb >= 0) atomicAdd(&g_pool[curb * 128 + pooloff + c], run);
}

// ---------------- classifier head: one block per graph -----------------------
__global__ void head_kernel(const float* __restrict__ wf,  const float* __restrict__ bf,
                            const float* __restrict__ wf1, const float* __restrict__ bf1,
                            const float* __restrict__ wf2, const float* __restrict__ bf2,
                            float* __restrict__ out)
{
    __shared__ float sg[128], a1[64], a2[64], lg[2];
    int g = blockIdx.x;
    int t = threadIdx.x;   // 64
    sg[t]      = g_pool[g * 128 + t];
    sg[t + 64] = g_pool[g * 128 + 64 + t];
    __syncthreads();
    float acc = bf[t];
    #pragma unroll 4
    for (int k = 0; k < 128; k++) acc += sg[k] * wf[k * 64 + t];
    a1[t] = fmaxf(acc, 0.f);
    __syncthreads();
    acc = bf1[t];
    #pragma unroll 4
    for (int k = 0; k < 64; k++) acc += a1[k] * wf1[k * 64 + t];
    a2[t] = fmaxf(acc, 0.f);
    __syncthreads();
    if (t < 2) {
        float l = bf2[t];
        for (int k = 0; k < 64; k++) l += a2[k] * wf2[k * 2 + t];
        lg[t] = l;
    }
    __syncthreads();
    if (t == 0) {
        float l0 = lg[0], l1 = lg[1];
        float m = fmaxf(l0, l1);
        float lse = m + logf(expf(l0 - m) + expf(l1 - m));
        out[g * 2 + 0] = l0 - lse;
        out[g * 2 + 1] = l1 - lse;
    }
}

// ---------------- launch -----------------------------------------------------
extern "C" void kernel_launch(void* const* d_in, const int* in_sizes, int n_in,
                              void* d_out, int out_size)
{
    const float* x     = (const float*)d_in[0];
    const void*  ei    = d_in[1];
    const float* ew    = (const float*)d_in[2];
    const void*  batch = d_in[3];
    const float* w1a = (const float*)d_in[4];
    const float* b1a = (const float*)d_in[5];
    const float* w2a = (const float*)d_in[6];
    const float* b2a = (const float*)d_in[7];
    const float* gm0 = (const float*)d_in[8];
    const float* bt0 = (const float*)d_in[9];
    const float* w1b = (const float*)d_in[10];
    const float* b1b = (const float*)d_in[11];
    const float* w2b = (const float*)d_in[12];
    const float* b2b = (const float*)d_in[13];
    const float* gm1 = (const float*)d_in[14];
    const float* bt1 = (const float*)d_in[15];
    const float* wf  = (const float*)d_in[16];
    const float* bf  = (const float*)d_in[17];
    const float* wf1 = (const float*)d_in[18];
    const float* bf1 = (const float*)d_in[19];
    const float* wf2 = (const float*)d_in[20];
    const float* bf2 = (const float*)d_in[21];
    float* out = (float*)d_out;

    float *pu, *pt, *pr, *ph, *pcs, *pcq;
    cudaGetSymbolAddress((void**)&pu,  g_u);
    cudaGetSymbolAddress((void**)&pt,  g_t);
    cudaGetSymbolAddress((void**)&pr,  g_r);
    cudaGetSymbolAddress((void**)&ph,  g_h);
    cudaGetSymbolAddress((void**)&pcs, g_colsum);
    cudaGetSymbolAddress((void**)&pcq, g_colsq);

    // -- prep
    detect_kernel<<<1, 32>>>(ei, batch);
    zero_kernel<<<(NN + 255) / 256, 256>>>();
    hist_kernel<<<(EE + 255) / 256, 256>>>(ei);
    scanA_kernel<<<NBLK, SCAN_BLK>>>();
    scanB_kernel<<<1, 32>>>();
    scanC_kernel<<<(NN + 255) / 256, 256>>>();
    fill_kernel<<<(EE + 255) / 256, 256>>>(ei, ew);

    int gemm_grid = (NN + 63) / 64;
    int agg_grid  = (NN * 32 + 255) / 256;

    // -- layer 0
    gemm_kernel<FF, false><<<gemm_grid, 256>>>(x, w1a, nullptr, pu, NN);   // u = x@w1a
    agg_kernel<<<agg_grid, 256>>>(pu, b1a, pt);                            // t = relu(u+agg+b1a)
    gemm_kernel<DD, true><<<gemm_grid, 256>>>(pt, w2a, b2a, pr, NN);       // r = relu(t@w2a+b2a)
    colstats_kernel<<<256, 256>>>(pr, pcs, pcq);
    bnpool_kernel<<<(NN + 127) / 128, 64>>>(pr, batch, gm0, bt0, pcs, pcq, ph, 0);

    // -- layer 1
    gemm_kernel<DD, false><<<gemm_grid, 256>>>(ph, w1b, nullptr, pu, NN);  // v = h@w1b
    agg_kernel<<<agg_grid, 256>>>(pu, b1b, pt);
    gemm_kernel<DD, true><<<gemm_grid, 256>>>(pt, w2b, b2b, pr, NN);
    colstats_kernel<<<256, 256>>>(pr, pcs + DD, pcq + DD);
    bnpool_kernel<<<(NN + 127) / 128, 64>>>(pr, batch, gm1, bt1, pcs + DD, pcq + DD,
                                            nullptr, DD);

    // -- head
    head_kernel<<<GG, 64>>>(wf, bf, wf1, bf1, wf2, bf2, out);
}

// round 5
// speedup vs baseline: 1.0269x; 1.0269x over previous
#include <cuda_runtime.h>
#include <math.h>

// Problem constants (fixed by the dataset)
#define NN 100000
#define EE 1600000
#define FF 128
#define DD 64
#define GG 512
#define SCAN_BLK 512
#define NBLK ((NN + SCAN_BLK - 1) / SCAN_BLK)   // 196
#define AS2S 260   // padded float stride of duplicated-A smem rows (k-major)

// ---------------- device scratch (static globals; no allocation) -------------
__device__ __align__(16) float g_u[NN * DD];
__device__ __align__(16) float g_t[NN * DD];
__device__ __align__(16) float g_r[NN * DD];
__device__ int   g_deg[NN];
__device__ int   g_off[NN];
__device__ int   g_cur[NN];
__device__ uint2 g_csr[EE];                    // {src, bitcast(weight)}
__device__ int   g_bsum[NBLK];
__device__ float g_colsum[2 * DD];
__device__ float g_colsq[2 * DD];
__device__ __align__(16) float g_pool[GG * 2 * DD];  // raw segment sums
__device__ int   g_cnt[GG];
__device__ float g_sc0[DD], g_sh0[DD], g_sc1[DD], g_sh1[DD];
__device__ __align__(16) float g_w1bp[DD * DD];      // diag(sc0) @ w1b
__device__ float g_bias1b[DD];                        // sh0 @ w1b  (NO b1b here!)
__device__ int   g_is64_ei;
__device__ int   g_is64_b;

// ---------------- helpers ----------------------------------------------------
__device__ __forceinline__ int ld_idx(const void* p, int i, int is64) {
    return is64 ? (int)((const long long*)p)[i] : ((const int*)p)[i];
}

// Packed 2xfp32 FMA. Primary path: single fma.rn.f32x2 (PTX ISA, sm_100a+).
// Fallback: two scalar FFMA on the packed halves (identical math).
__device__ __forceinline__ unsigned long long fma2(unsigned long long a,
                                                   unsigned long long b,
                                                   unsigned long long c) {
#if defined(__CUDA_ARCH__) && (__CUDA_ARCH__ >= 1000)
    unsigned long long d;
    asm("fma.rn.f32x2 %0, %1, %2, %3;" : "=l"(d) : "l"(a), "l"(b), "l"(c));
    return d;
#else
    float ax = __uint_as_float((unsigned)(a & 0xffffffffull));
    float ay = __uint_as_float((unsigned)(a >> 32));
    float bx = __uint_as_float((unsigned)(b & 0xffffffffull));
    float by = __uint_as_float((unsigned)(b >> 32));
    float cx = __uint_as_float((unsigned)(c & 0xffffffffull));
    float cy = __uint_as_float((unsigned)(c >> 32));
    float dx = fmaf(ax, bx, cx);
    float dy = fmaf(ay, by, cy);
    return ((unsigned long long)__float_as_uint(dy) << 32) |
           (unsigned long long)__float_as_uint(dx);
#endif
}

__device__ __forceinline__ float2 unpk(unsigned long long v) {
    float2 r;
    r.x = __uint_as_float((unsigned)(v & 0xffffffffull));
    r.y = __uint_as_float((unsigned)(v >> 32));
    return r;
}

// ---------------- init + dtype sniffing --------------------------------------
__global__ void init_kernel(const void* ei, const void* batch) {
    int i = blockIdx.x * blockDim.x + threadIdx.x;
    if (i < NN) g_deg[i] = 0;
    if (i < 2 * DD) { g_colsum[i] = 0.f; g_colsq[i] = 0.f; }
    if (i < GG * 2 * DD) g_pool[i] = 0.f;
    if (i < GG) g_cnt[i] = 0;
    if (i == 0) {
        const int* p = (const int*)ei;
        int nz = 0;
        #pragma unroll
        for (int k = 0; k < 16; k++) {
            int j = 1000 + k * 9973;
            if (p[2 * j + 1] != 0) nz++;
        }
        g_is64_ei = (nz == 0) ? 1 : 0;
        const int* q = (const int*)batch;
        int nz2 = 0;
        #pragma unroll
        for (int k = 0; k < 16; k++) {
            int j = 40000 + k * 601;
            if (q[2 * j + 1] != 0) nz2++;
        }
        g_is64_b = (nz2 == 0) ? 1 : 0;
    }
}

// ---------------- CSR build --------------------------------------------------
__global__ void hist_kernel(const void* ei) {
    int e = blockIdx.x * blockDim.x + threadIdx.x;
    if (e >= EE) return;
    int is64 = g_is64_ei;
    int d = ld_idx(ei, EE + e, is64);
    atomicAdd(&g_deg[d], 1);
}

__global__ void scanA_kernel() {
    __shared__ int s[SCAN_BLK];
    int t = threadIdx.x;
    int i = blockIdx.x * SCAN_BLK + t;
    int v = (i < NN) ? g_deg[i] : 0;
    s[t] = v;
    __syncthreads();
    for (int off = 1; off < SCAN_BLK; off <<= 1) {
        int add = (t >= off) ? s[t - off] : 0;
        __syncthreads();
        s[t] += add;
        __syncthreads();
    }
    if (i < NN) g_off[i] = s[t] - v;            // exclusive (block-local)
    if (t == SCAN_BLK - 1) g_bsum[blockIdx.x] = s[SCAN_BLK - 1];
}

// parallel 256-thread scan over the 196 block sums
__global__ void scanB_kernel() {
    __shared__ int s[256];
    int t = threadIdx.x;
    int v = (t < NBLK) ? g_bsum[t] : 0;
    s[t] = v;
    __syncthreads();
    for (int off = 1; off < 256; off <<= 1) {
        int add = (t >= off) ? s[t - off] : 0;
        __syncthreads();
        s[t] += add;
        __syncthreads();
    }
    if (t < NBLK) g_bsum[t] = s[t] - v;         // exclusive
}

__global__ void scanC_kernel() {
    int i = blockIdx.x * blockDim.x + threadIdx.x;
    if (i >= NN) return;
    int o = g_off[i] + g_bsum[i >> 9];
    g_off[i] = o;
    g_cur[i] = o;
}

__global__ void fill_kernel(const void* ei, const float* __restrict__ ew) {
    int e = blockIdx.x * blockDim.x + threadIdx.x;
    if (e >= EE) return;
    int is64 = g_is64_ei;
    int s = ld_idx(ei, e, is64);
    int d = ld_idx(ei, EE + e, is64);
    int pos = atomicAdd(&g_cur[d], 1);
    g_csr[pos] = make_uint2((unsigned)s, __float_as_uint(ew[e]));
}

// ---------------- GEMM: C[n][c] = act(sum_k A[n][k] W[k][c] + bias[c]) -------
// 256 threads, tile 128 rows x 64 cols, per thread 8 rows x 4 cols.
// A staged k-major DUPLICATED in smem so LDS.128 yields packed f32x2 broadcast
// operands directly; W read as double2 = packed column pairs. fma.rn.f32x2.
// Optional fused column stats (sum, sumsq) for BN.
template <int K, bool RELU, bool STATS>
__global__ void __launch_bounds__(256) gemm_kernel(
    const float* __restrict__ A, const float* __restrict__ W,
    const float* __restrict__ bias, float* __restrict__ C,
    float* __restrict__ csum, float* __restrict__ csq, int nrows)
{
    __shared__ __align__(16) float As2[32 * AS2S];   // [k][2*row] duplicated
    __shared__ __align__(16) float Ws[32 * 64];
    int t  = threadIdx.x;
    int cg = t & 15;                   // cols 4*cg .. 4*cg+3
    int rg = t >> 4;                   // rows 8*rg .. 8*rg+7
    int n0 = blockIdx.x * 128;

    unsigned long long acc[8][2];
    #pragma unroll
    for (int i = 0; i < 8; i++) { acc[i][0] = 0ull; acc[i][1] = 0ull; }

    for (int kc = 0; kc < K; kc += 32) {
        // load A chunk (coalesced), store transposed + duplicated
        #pragma unroll
        for (int j = 0; j < 4; j++) {
            int idx = t + j * 256;     // 0..1023 float4s
            int r   = idx >> 3;        // 0..127
            int f4  = idx & 7;         // 0..7 -> k offsets 4*f4..4*f4+3
            float4 v = make_float4(0.f, 0.f, 0.f, 0.f);
            int row = n0 + r;
            if (row < nrows)
                v = *(const float4*)&A[(size_t)row * K + kc + 4 * f4];
            *(float2*)&As2[(4 * f4 + 0) * AS2S + 2 * r] = make_float2(v.x, v.x);
            *(float2*)&As2[(4 * f4 + 1) * AS2S + 2 * r] = make_float2(v.y, v.y);
            *(float2*)&As2[(4 * f4 + 2) * AS2S + 2 * r] = make_float2(v.z, v.z);
            *(float2*)&As2[(4 * f4 + 3) * AS2S + 2 * r] = make_float2(v.w, v.w);
        }
        // load W chunk (coalesced)
        #pragma unroll
        for (int j = 0; j < 2; j++) {
            int idx = t + j * 256;     // 0..511 float4s
            int kr  = idx >> 4;        // 0..31
            int c4  = idx & 15;
            *(float4*)&Ws[kr * 64 + 4 * c4] =
                *(const float4*)&W[(size_t)(kc + kr) * DD + 4 * c4];
        }
        __syncthreads();

        #pragma unroll
        for (int k = 0; k < 32; k++) {
            const double2* ap = (const double2*)&As2[k * AS2S + 16 * rg];
            double2 a01 = ap[0], a23 = ap[1], a45 = ap[2], a67 = ap[3];
            double2 wp  = *(const double2*)&Ws[k * 64 + 4 * cg];
            unsigned long long w0 = __double_as_longlong(wp.x);
            unsigned long long w1 = __double_as_longlong(wp.y);
            unsigned long long a[8] = {
                __double_as_longlong(a01.x), __double_as_longlong(a01.y),
                __double_as_longlong(a23.x), __double_as_longlong(a23.y),
                __double_as_longlong(a45.x), __double_as_longlong(a45.y),
                __double_as_longlong(a67.x), __double_as_longlong(a67.y)};
            #pragma unroll
            for (int i = 0; i < 8; i++) {
                acc[i][0] = fma2(a[i], w0, acc[i][0]);
                acc[i][1] = fma2(a[i], w1, acc[i][1]);
            }
        }
        __syncthreads();
    }

    float4 b4 = bias ? *(const float4*)&bias[4 * cg]
                     : make_float4(0.f, 0.f, 0.f, 0.f);
    float s0 = 0.f, s1 = 0.f, s2 = 0.f, s3 = 0.f;
    float q0 = 0.f, q1 = 0.f, q2 = 0.f, q3 = 0.f;
    #pragma unroll
    for (int i = 0; i < 8; i++) {
        int row = n0 + 8 * rg + i;
        float2 p0 = unpk(acc[i][0]);
        float2 p1 = unpk(acc[i][1]);
        float o0 = p0.x + b4.x, o1 = p0.y + b4.y;
        float o2 = p1.x + b4.z, o3 = p1.y + b4.w;
        if (RELU) {
            o0 = fmaxf(o0, 0.f); o1 = fmaxf(o1, 0.f);
            o2 = fmaxf(o2, 0.f); o3 = fmaxf(o3, 0.f);
        }
        if (row < nrows) {
            float4 o = make_float4(o0, o1, o2, o3);
            *(float4*)&C[(size_t)row * DD + 4 * cg] = o;
            if (STATS) {
                s0 += o0; s1 += o1; s2 += o2; s3 += o3;
                q0 += o0 * o0; q1 += o1 * o1; q2 += o2 * o2; q3 += o3 * o3;
            }
        }
    }

    if (STATS) {
        // Ws is dead now (synced after last chunk) — reuse as reduction scratch
        float* redS = Ws;              // [16][64]
        float* redQ = Ws + 1024;       // [16][64]
        redS[rg * 64 + 4 * cg + 0] = s0; redS[rg * 64 + 4 * cg + 1] = s1;
        redS[rg * 64 + 4 * cg + 2] = s2; redS[rg * 64 + 4 * cg + 3] = s3;
        redQ[rg * 64 + 4 * cg + 0] = q0; redQ[rg * 64 + 4 * cg + 1] = q1;
        redQ[rg * 64 + 4 * cg + 2] = q2; redQ[rg * 64 + 4 * cg + 3] = q3;
        __syncthreads();
        if (t < 64) {
            float S = 0.f, Q = 0.f;
            #pragma unroll
            for (int g = 0; g < 16; g++) {
                S += redS[g * 64 + t];
                Q += redQ[g * 64 + t];
            }
            atomicAdd(&csum[t], S);
            atomicAdd(&csq[t], Q);
        }
    }
}

// ---------------- aggregation: one warp per node, CSR gather, no atomics -----
// T[node] = relu(U[node] + sum_e w_e * U[src_e] + bias)   (bias per-column)
__global__ void __launch_bounds__(256) agg_kernel(
    const float* __restrict__ U, const float* __restrict__ bias,
    float* __restrict__ T)
{
    int w = (blockIdx.x * blockDim.x + threadIdx.x) >> 5;
    int lane = threadIdx.x & 31;
    if (w >= NN) return;
    int s  = g_off[w];
    int dg = g_deg[w];
    float a0 = 0.f, a1 = 0.f;
    int e = 0;
    for (; e + 4 <= dg; e += 4) {
        uint2 c0 = g_csr[s + e + 0];
        uint2 c1 = g_csr[s + e + 1];
        uint2 c2 = g_csr[s + e + 2];
        uint2 c3 = g_csr[s + e + 3];
        float2 v0 = *(const float2*)(U + (size_t)c0.x * DD + 2 * lane);
        float2 v1 = *(const float2*)(U + (size_t)c1.x * DD + 2 * lane);
        float2 v2 = *(const float2*)(U + (size_t)c2.x * DD + 2 * lane);
        float2 v3 = *(const float2*)(U + (size_t)c3.x * DD + 2 * lane);
        float w0 = __uint_as_float(c0.y), w1 = __uint_as_float(c1.y);
        float w2 = __uint_as_float(c2.y), w3 = __uint_as_float(c3.y);
        a0 += w0 * v0.x; a1 += w0 * v0.y;
        a0 += w1 * v1.x; a1 += w1 * v1.y;
        a0 += w2 * v2.x; a1 += w2 * v2.y;
        a0 += w3 * v3.x; a1 += w3 * v3.y;
    }
    for (; e < dg; e++) {
        uint2 c = g_csr[s + e];
        float2 v = *(const float2*)(U + (size_t)c.x * DD + 2 * lane);
        float ww = __uint_as_float(c.y);
        a0 += ww * v.x; a1 += ww * v.y;
    }
    float2 u2 = *(const float2*)(U + (size_t)w * DD + 2 * lane);
    float b0 = bias[2 * lane], b1 = bias[2 * lane + 1];
    float2 o;
    o.x = fmaxf(u2.x + a0 + b0, 0.f);
    o.y = fmaxf(u2.y + a1 + b1, 0.f);
    *(float2*)(T + (size_t)w * DD + 2 * lane) = o;
}

// ---------------- finalize BN affine + fold into next-layer weights ----------
// h = sc0∘r + sh0 (per column). Layer-1 transform:
//   u = h@w1b = r@(diag(sc0)·w1b) + sh0@w1b
// The sh0@w1b constant is INSIDE u (it's part of h), so it must be present in
// the gathered messages ew·u[src] as well -> fold it into the GEMM bias.
// The plain MLP bias b1b is added once per node AFTER aggregation.
__global__ void fin0_kernel(const float* __restrict__ gamma,
                            const float* __restrict__ beta,
                            const float* __restrict__ w1b)
{
    __shared__ float ssc[64], ssh[64];
    int t = threadIdx.x;
    if (t < 64) {
        float mean = g_colsum[t] * (1.f / NN);
        float var  = g_colsq[t] * (1.f / NN) - mean * mean;
        float sc = gamma[t] * rsqrtf(var + 1e-5f);
        float sh = beta[t] - mean * sc;
        g_sc0[t] = sc; g_sh0[t] = sh;
        ssc[t] = sc; ssh[t] = sh;
    }
    __syncthreads();
    #pragma unroll
    for (int j = 0; j < 16; j++) {
        int e = t + j * 256;           // 0..4095
        int k = e >> 6;
        g_w1bp[e] = ssc[k] * w1b[e];
    }
    if (t < 64) {
        float b = 0.f;                 // sh0 @ w1b only — b1b applied post-agg
        #pragma unroll 8
        for (int k = 0; k < 64; k++) b += ssh[k] * w1b[k * 64 + t];
        g_bias1b[t] = b;
    }
}

__global__ void fin1_kernel(const float* __restrict__ gamma,
                            const float* __restrict__ beta)
{
    int t = threadIdx.x;
    if (t < 64) {
        float mean = g_colsum[64 + t] * (1.f / NN);
        float var  = g_colsq[64 + t] * (1.f / NN) - mean * mean;
        float sc = gamma[t] * rsqrtf(var + 1e-5f);
        g_sc1[t] = sc;
        g_sh1[t] = beta[t] - mean * sc;
    }
}

// ---------------- raw segment-sum pool (batch sorted -> run-length) ----------
__global__ void pool_kernel(const float* __restrict__ R, const void* batch,
                            int pooloff, int docnt)
{
    const int NCH = 128;
    int c  = threadIdx.x;              // 64 threads, one per column
    int n0 = blockIdx.x * NCH;
    int is64 = g_is64_b;
    float run = 0.f;
    int len = 0;
    int curb = -1;
    int n1 = min(n0 + NCH, NN);
    for (int n = n0; n < n1; n++) {
        int b = ld_idx(batch, n, is64);
        float v = R[(size_t)n * DD + c];
        if (b != curb) {
            if (curb >= 0) {
                atomicAdd(&g_pool[curb * 128 + pooloff + c], run);
                if (docnt && c == 0) atomicAdd(&g_cnt[curb], len);
            }
            run = 0.f; len = 0;
            curb = b;
        }
        run += v; len++;
    }
    if (curb >= 0) {
        atomicAdd(&g_pool[curb * 128 + pooloff + c], run);
        if (docnt && c == 0) atomicAdd(&g_cnt[curb], len);
    }
}

// ---------------- classifier head: one block per graph -----------------------
// pool(BN(r)) = sc∘pool(r) + cnt·sh  (applied here, pools stored raw)
__global__ void head_kernel(const float* __restrict__ wf,  const float* __restrict__ bf,
                            const float* __restrict__ wf1, const float* __restrict__ bf1,
                            const float* __restrict__ wf2, const float* __restrict__ bf2,
                            float* __restrict__ out)
{
    __shared__ float sg[128], a1[64], a2[64], lg[2];
    int g = blockIdx.x;
    int t = threadIdx.x;   // 64
    float cnt = (float)g_cnt[g];
    sg[t]      = g_sc0[t] * g_pool[g * 128 + t]      + cnt * g_sh0[t];
    sg[t + 64] = g_sc1[t] * g_pool[g * 128 + 64 + t] + cnt * g_sh1[t];
    __syncthreads();
    float acc = bf[t];
    #pragma unroll 4
    for (int k = 0; k < 128; k++) acc += sg[k] * wf[k * 64 + t];
    a1[t] = fmaxf(acc, 0.f);
    __syncthreads();
    acc = bf1[t];
    #pragma unroll 4
    for (int k = 0; k < 64; k++) acc += a1[k] * wf1[k * 64 + t];
    a2[t] = fmaxf(acc, 0.f);
    __syncthreads();
    if (t < 2) {
        float l = bf2[t];
        for (int k = 0; k < 64; k++) l += a2[k] * wf2[k * 2 + t];
        lg[t] = l;
    }
    __syncthreads();
    if (t == 0) {
        float l0 = lg[0], l1 = lg[1];
        float m = fmaxf(l0, l1);
        float lse = m + logf(expf(l0 - m) + expf(l1 - m));
        out[g * 2 + 0] = l0 - lse;
        out[g * 2 + 1] = l1 - lse;
    }
}

// ---------------- launch -----------------------------------------------------
extern "C" void kernel_launch(void* const* d_in, const int* in_sizes, int n_in,
                              void* d_out, int out_size)
{
    const float* x     = (const float*)d_in[0];
    const void*  ei    = d_in[1];
    const float* ew    = (const float*)d_in[2];
    const void*  batch = d_in[3];
    const float* w1a = (const float*)d_in[4];
    const float* b1a = (const float*)d_in[5];
    const float* w2a = (const float*)d_in[6];
    const float* b2a = (const float*)d_in[7];
    const float* gm0 = (const float*)d_in[8];
    const float* bt0 = (const float*)d_in[9];
    const float* w1b = (const float*)d_in[10];
    const float* b1b = (const float*)d_in[11];
    const float* w2b = (const float*)d_in[12];
    const float* b2b = (const float*)d_in[13];
    const float* gm1 = (const float*)d_in[14];
    const float* bt1 = (const float*)d_in[15];
    const float* wf  = (const float*)d_in[16];
    const float* bf  = (const float*)d_in[17];
    const float* wf1 = (const float*)d_in[18];
    const float* bf1 = (const float*)d_in[19];
    const float* wf2 = (const float*)d_in[20];
    const float* bf2 = (const float*)d_in[21];
    float* out = (float*)d_out;

    float *pu, *pt, *pr, *pcs, *pcq, *pw1bp, *pb1b;
    cudaGetSymbolAddress((void**)&pu,  g_u);
    cudaGetSymbolAddress((void**)&pt,  g_t);
    cudaGetSymbolAddress((void**)&pr,  g_r);
    cudaGetSymbolAddress((void**)&pcs, g_colsum);
    cudaGetSymbolAddress((void**)&pcq, g_colsq);
    cudaGetSymbolAddress((void**)&pw1bp, g_w1bp);
    cudaGetSymbolAddress((void**)&pb1b,  g_bias1b);

    // -- prep
    init_kernel<<<(NN + 255) / 256, 256>>>(ei, batch);
    hist_kernel<<<(EE + 255) / 256, 256>>>(ei);
    scanA_kernel<<<NBLK, SCAN_BLK>>>();
    scanB_kernel<<<1, 256>>>();
    scanC_kernel<<<(NN + 255) / 256, 256>>>();
    fill_kernel<<<(EE + 255) / 256, 256>>>(ei, ew);

    int gemm_grid = (NN + 127) / 128;
    int agg_grid  = (NN * 32 + 255) / 256;
    int pool_grid = (NN + 127) / 128;

    // -- layer 0
    gemm_kernel<FF, false, false><<<gemm_grid, 256>>>(x, w1a, nullptr, pu,
                                                      nullptr, nullptr, NN);
    agg_kernel<<<agg_grid, 256>>>(pu, b1a, pt);
    gemm_kernel<DD, true, true><<<gemm_grid, 256>>>(pt, w2a, b2a, pr,
                                                    pcs, pcq, NN);
    fin0_kernel<<<1, 256>>>(gm0, bt0, w1b);
    pool_kernel<<<pool_grid, 64>>>(pr, batch, 0, 1);

    // -- layer 1: u = h@w1b exactly (bias sh0@w1b inside GEMM so messages
    //             carry it too); plain MLP bias b1b added post-aggregation
    gemm_kernel<DD, false, false><<<gemm_grid, 256>>>(pr, pw1bp, pb1b, pu,
                                                      nullptr, nullptr, NN);
    agg_kernel<<<agg_grid, 256>>>(pu, b1b, pt);
    gemm_kernel<DD, true, true><<<gemm_grid, 256>>>(pt, w2b, b2b, pr,
                                                    pcs + DD, pcq + DD, NN);
    fin1_kernel<<<1, 64>>>(gm1, bt1);
    pool_kernel<<<pool_grid, 64>>>(pr, batch, DD, 0);

    // -- head
    head_kernel<<<GG, 64>>>(wf, bf, wf1, bf1, wf2, bf2, out);
}

// round 6
// speedup vs baseline: 1.1626x; 1.1322x over previous
#include <cuda_runtime.h>
#include <math.h>

// Problem constants (fixed by the dataset)
#define NN 100000
#define EE 1600000
#define FF 128
#define DD 64
#define GG 512
#define SCAN_BLK 512
#define NBLK ((NN + SCAN_BLK - 1) / SCAN_BLK)   // 196
#define AS2S 260   // padded float stride of duplicated-A smem rows (k-major)
#define NSLOT 8    // graph slots per gemm block for fused pooling

// ---------------- device scratch (static globals; no allocation) -------------
__device__ __align__(16) float g_u[NN * DD];
__device__ __align__(16) float g_t[NN * DD];
__device__ __align__(16) float g_r[NN * DD];
__device__ int   g_deg[NN];
__device__ int   g_off[NN];
__device__ int   g_cur[NN];
__device__ uint2 g_csr[EE];                    // {src, bitcast(weight)}
__device__ int   g_bsum[NBLK];
__device__ float g_colsum[2 * DD];
__device__ float g_colsq[2 * DD];
__device__ __align__(16) float g_pool[GG * 2 * DD];  // raw segment sums
__device__ int   g_cnt[GG];
__device__ float g_sc0[DD], g_sh0[DD];
__device__ __align__(16) float g_w1bp[DD * DD];      // diag(sc0) @ w1b
__device__ float g_bias1b[DD];                        // sh0 @ w1b
__device__ int   g_is64_ei;
__device__ int   g_is64_b;

// ---------------- helpers ----------------------------------------------------
__device__ __forceinline__ int ld_idx(const void* p, int i, int is64) {
    return is64 ? (int)((const long long*)p)[i] : ((const int*)p)[i];
}

// Packed 2xfp32 FMA. Primary path: single fma.rn.f32x2 (PTX ISA, sm_100a+).
__device__ __forceinline__ unsigned long long fma2(unsigned long long a,
                                                   unsigned long long b,
                                                   unsigned long long c) {
#if defined(__CUDA_ARCH__) && (__CUDA_ARCH__ >= 1000)
    unsigned long long d;
    asm("fma.rn.f32x2 %0, %1, %2, %3;" : "=l"(d) : "l"(a), "l"(b), "l"(c));
    return d;
#else
    float ax = __uint_as_float((unsigned)(a & 0xffffffffull));
    float ay = __uint_as_float((unsigned)(a >> 32));
    float bx = __uint_as_float((unsigned)(b & 0xffffffffull));
    float by = __uint_as_float((unsigned)(b >> 32));
    float cx = __uint_as_float((unsigned)(c & 0xffffffffull));
    float cy = __uint_as_float((unsigned)(c >> 32));
    float dx = fmaf(ax, bx, cx);
    float dy = fmaf(ay, by, cy);
    return ((unsigned long long)__float_as_uint(dy) << 32) |
           (unsigned long long)__float_as_uint(dx);
#endif
}

__device__ __forceinline__ float2 unpk(unsigned long long v) {
    float2 r;
    r.x = __uint_as_float((unsigned)(v & 0xffffffffull));
    r.y = __uint_as_float((unsigned)(v >> 32));
    return r;
}

// ---------------- init + dtype sniffing --------------------------------------
__global__ void init_kernel(const void* ei, const void* batch) {
    int i = blockIdx.x * blockDim.x + threadIdx.x;
    if (i < NN) g_deg[i] = 0;
    if (i < 2 * DD) { g_colsum[i] = 0.f; g_colsq[i] = 0.f; }
    if (i < GG * 2 * DD) g_pool[i] = 0.f;
    if (i < GG) g_cnt[i] = 0;
    if (i == 0) {
        const int* p = (const int*)ei;
        int nz = 0;
        #pragma unroll
        for (int k = 0; k < 16; k++) {
            int j = 1000 + k * 9973;
            if (p[2 * j + 1] != 0) nz++;
        }
        g_is64_ei = (nz == 0) ? 1 : 0;
        const int* q = (const int*)batch;
        int nz2 = 0;
        #pragma unroll
        for (int k = 0; k < 16; k++) {
            int j = 40000 + k * 601;
            if (q[2 * j + 1] != 0) nz2++;
        }
        g_is64_b = (nz2 == 0) ? 1 : 0;
    }
}

// ---------------- CSR build --------------------------------------------------
__global__ void hist_kernel(const void* ei) {
    int e = blockIdx.x * blockDim.x + threadIdx.x;
    if (e >= EE) return;
    int is64 = g_is64_ei;
    int d = ld_idx(ei, EE + e, is64);
    atomicAdd(&g_deg[d], 1);
}

__global__ void scanA_kernel() {
    __shared__ int s[SCAN_BLK];
    int t = threadIdx.x;
    int i = blockIdx.x * SCAN_BLK + t;
    int v = (i < NN) ? g_deg[i] : 0;
    s[t] = v;
    __syncthreads();
    for (int off = 1; off < SCAN_BLK; off <<= 1) {
        int add = (t >= off) ? s[t - off] : 0;
        __syncthreads();
        s[t] += add;
        __syncthreads();
    }
    if (i < NN) g_off[i] = s[t] - v;            // exclusive (block-local)
    if (t == SCAN_BLK - 1) g_bsum[blockIdx.x] = s[SCAN_BLK - 1];
}

// scanC with inline block-sum scan (fused former scanB): every block
// redundantly scans the 196 block sums in smem — 196 loads, trivial.
__global__ void scanC_kernel() {
    __shared__ int sb[256];
    int t = threadIdx.x;
    int v = (t < NBLK) ? g_bsum[t] : 0;
    sb[t] = v;
    __syncthreads();
    for (int off = 1; off < 256; off <<= 1) {
        int add = (t >= off) ? sb[t - off] : 0;
        __syncthreads();
        sb[t] += add;                  // inclusive scan
        __syncthreads();
    }
    int i = blockIdx.x * blockDim.x + t;
    if (i < NN) {
        int j = i >> 9;                // scan-block of 512 nodes
        int pre = (j == 0) ? 0 : sb[j - 1];
        int o = g_off[i] + pre;
        g_off[i] = o;
        g_cur[i] = o;
    }
}

__global__ void fill_kernel(const void* ei, const float* __restrict__ ew) {
    int e = blockIdx.x * blockDim.x + threadIdx.x;
    if (e >= EE) return;
    int is64 = g_is64_ei;
    int s = ld_idx(ei, e, is64);
    int d = ld_idx(ei, EE + e, is64);
    int pos = atomicAdd(&g_cur[d], 1);
    g_csr[pos] = make_uint2((unsigned)s, __float_as_uint(ew[e]));
}

// ---------------- GEMM: C[n][c] = act(sum_k A[n][k] W[k][c] + bias[c]) -------
// 256 threads, tile 128 rows x 64 cols, per thread 8 rows x 4 cols.
// A staged k-major DUPLICATED in smem so LDS.128 yields packed f32x2 broadcast
// operands directly; W read as double2 = packed column pairs. fma.rn.f32x2.
// STATS variant also fuses column stats (sum,sumsq) AND segment-sum pooling
// (batch is sorted; block spans few graphs -> smem slots, global fallback).
template <int K, bool RELU, bool STATS>
__global__ void __launch_bounds__(256) gemm_kernel(
    const float* __restrict__ A, const float* __restrict__ W,
    const float* __restrict__ bias, float* __restrict__ C,
    float* __restrict__ csum, float* __restrict__ csq,
    const void* batch, int pooloff, int docnt, int nrows)
{
    __shared__ __align__(16) float As2[32 * AS2S];   // [k][2*row] duplicated
    __shared__ __align__(16) float Ws[32 * 64];
    __shared__ float spool[NSLOT * 64];
    __shared__ int   scnt[NSLOT];
    __shared__ int   sbatch[128];
    int t  = threadIdx.x;
    int cg = t & 15;                   // cols 4*cg .. 4*cg+3
    int rg = t >> 4;                   // rows 8*rg .. 8*rg+7
    int n0 = blockIdx.x * 128;

    if (STATS) {
        for (int j = t; j < NSLOT * 64; j += 256) spool[j] = 0.f;
        if (t < NSLOT) scnt[t] = 0;
        if (t < 128) {
            int row = n0 + t;
            sbatch[t] = (row < nrows) ? ld_idx(batch, row, g_is64_b) : -1;
        }
        // first k-chunk __syncthreads() orders these before any use
    }

    unsigned long long acc[8][2];
    #pragma unroll
    for (int i = 0; i < 8; i++) { acc[i][0] = 0ull; acc[i][1] = 0ull; }

    for (int kc = 0; kc < K; kc += 32) {
        // load A chunk (coalesced), store transposed + duplicated
        #pragma unroll
        for (int j = 0; j < 4; j++) {
            int idx = t + j * 256;     // 0..1023 float4s
            int r   = idx >> 3;        // 0..127
            int f4  = idx & 7;         // 0..7 -> k offsets 4*f4..4*f4+3
            float4 v = make_float4(0.f, 0.f, 0.f, 0.f);
            int row = n0 + r;
            if (row < nrows)
                v = *(const float4*)&A[(size_t)row * K + kc + 4 * f4];
            *(float2*)&As2[(4 * f4 + 0) * AS2S + 2 * r] = make_float2(v.x, v.x);
            *(float2*)&As2[(4 * f4 + 1) * AS2S + 2 * r] = make_float2(v.y, v.y);
            *(float2*)&As2[(4 * f4 + 2) * AS2S + 2 * r] = make_float2(v.z, v.z);
            *(float2*)&As2[(4 * f4 + 3) * AS2S + 2 * r] = make_float2(v.w, v.w);
        }
        // load W chunk (coalesced)
        #pragma unroll
        for (int j = 0; j < 2; j++) {
            int idx = t + j * 256;     // 0..511 float4s
            int kr  = idx >> 4;        // 0..31
            int c4  = idx & 15;
            *(float4*)&Ws[kr * 64 + 4 * c4] =
                *(const float4*)&W[(size_t)(kc + kr) * DD + 4 * c4];
        }
        __syncthreads();

        #pragma unroll
        for (int k = 0; k < 32; k++) {
            const double2* ap = (const double2*)&As2[k * AS2S + 16 * rg];
            double2 a01 = ap[0], a23 = ap[1], a45 = ap[2], a67 = ap[3];
            double2 wp  = *(const double2*)&Ws[k * 64 + 4 * cg];
            unsigned long long w0 = __double_as_longlong(wp.x);
            unsigned long long w1 = __double_as_longlong(wp.y);
            unsigned long long a[8] = {
                __double_as_longlong(a01.x), __double_as_longlong(a01.y),
                __double_as_longlong(a23.x), __double_as_longlong(a23.y),
                __double_as_longlong(a45.x), __double_as_longlong(a45.y),
                __double_as_longlong(a67.x), __double_as_longlong(a67.y)};
            #pragma unroll
            for (int i = 0; i < 8; i++) {
                acc[i][0] = fma2(a[i], w0, acc[i][0]);
                acc[i][1] = fma2(a[i], w1, acc[i][1]);
            }
        }
        __syncthreads();
    }

    float4 b4 = bias ? *(const float4*)&bias[4 * cg]
                     : make_float4(0.f, 0.f, 0.f, 0.f);
    float s0 = 0.f, s1 = 0.f, s2 = 0.f, s3 = 0.f;
    float q0 = 0.f, q1 = 0.f, q2 = 0.f, q3 = 0.f;
    // run-length pooling state (rows sorted by graph)
    int b0blk = STATS ? sbatch[0] : 0;
    int curslot = -1, rl = 0;
    float r0 = 0.f, r1 = 0.f, r2 = 0.f, r3 = 0.f;

    #pragma unroll
    for (int i = 0; i < 8; i++) {
        int row = n0 + 8 * rg + i;
        float2 p0 = unpk(acc[i][0]);
        float2 p1 = unpk(acc[i][1]);
        float o0 = p0.x + b4.x, o1 = p0.y + b4.y;
        float o2 = p1.x + b4.z, o3 = p1.y + b4.w;
        if (RELU) {
            o0 = fmaxf(o0, 0.f); o1 = fmaxf(o1, 0.f);
            o2 = fmaxf(o2, 0.f); o3 = fmaxf(o3, 0.f);
        }
        if (row < nrows) {
            float4 o = make_float4(o0, o1, o2, o3);
            *(float4*)&C[(size_t)row * DD + 4 * cg] = o;
            if (STATS) {
                s0 += o0; s1 += o1; s2 += o2; s3 += o3;
                q0 += o0 * o0; q1 += o1 * o1; q2 += o2 * o2; q3 += o3 * o3;
                int slot = sbatch[8 * rg + i] - b0blk;
                if (slot != curslot) {
                    if (curslot >= 0) {
                        if (curslot < NSLOT) {
                            atomicAdd(&spool[curslot * 64 + 4 * cg + 0], r0);
                            atomicAdd(&spool[curslot * 64 + 4 * cg + 1], r1);
                            atomicAdd(&spool[curslot * 64 + 4 * cg + 2], r2);
                            atomicAdd(&spool[curslot * 64 + 4 * cg + 3], r3);
                            if (docnt && cg == 0) atomicAdd(&scnt[curslot], rl);
                        } else {
                            int b = b0blk + curslot;
                            atomicAdd(&g_pool[b * 128 + pooloff + 4 * cg + 0], r0);
                            atomicAdd(&g_pool[b * 128 + pooloff + 4 * cg + 1], r1);
                            atomicAdd(&g_pool[b * 128 + pooloff + 4 * cg + 2], r2);
                            atomicAdd(&g_pool[b * 128 + pooloff + 4 * cg + 3], r3);
                            if (docnt && cg == 0) atomicAdd(&g_cnt[b], rl);
                        }
                    }
                    curslot = slot; rl = 0;
                    r0 = r1 = r2 = r3 = 0.f;
                }
                r0 += o0; r1 += o1; r2 += o2; r3 += o3; rl++;
            }
        }
    }
    if (STATS && curslot >= 0) {
        if (curslot < NSLOT) {
            atomicAdd(&spool[curslot * 64 + 4 * cg + 0], r0);
            atomicAdd(&spool[curslot * 64 + 4 * cg + 1], r1);
            atomicAdd(&spool[curslot * 64 + 4 * cg + 2], r2);
            atomicAdd(&spool[curslot * 64 + 4 * cg + 3], r3);
            if (docnt && cg == 0) atomicAdd(&scnt[curslot], rl);
        } else {
            int b = b0blk + curslot;
            atomicAdd(&g_pool[b * 128 + pooloff + 4 * cg + 0], r0);
            atomicAdd(&g_pool[b * 128 + pooloff + 4 * cg + 1], r1);
            atomicAdd(&g_pool[b * 128 + pooloff + 4 * cg + 2], r2);
            atomicAdd(&g_pool[b * 128 + pooloff + 4 * cg + 3], r3);
            if (docnt && cg == 0) atomicAdd(&g_cnt[b], rl);
        }
    }

    if (STATS) {
        // Ws is dead now (synced after last chunk) — reuse as reduction scratch
        float* redS = Ws;              // [16][64]
        float* redQ = Ws + 1024;       // [16][64]
        redS[rg * 64 + 4 * cg + 0] = s0; redS[rg * 64 + 4 * cg + 1] = s1;
        redS[rg * 64 + 4 * cg + 2] = s2; redS[rg * 64 + 4 * cg + 3] = s3;
        redQ[rg * 64 + 4 * cg + 0] = q0; redQ[rg * 64 + 4 * cg + 1] = q1;
        redQ[rg * 64 + 4 * cg + 2] = q2; redQ[rg * 64 + 4 * cg + 3] = q3;
        __syncthreads();
        if (t < 64) {
            float S = 0.f, Q = 0.f;
            #pragma unroll
            for (int g = 0; g < 16; g++) {
                S += redS[g * 64 + t];
                Q += redQ[g * 64 + t];
            }
            atomicAdd(&csum[t], S);
            atomicAdd(&csq[t], Q);
        }
        // flush smem pool slots to global (zero-skip also guards absent slots)
        for (int j = t; j < NSLOT * 64; j += 256) {
            float v = spool[j];
            if (v != 0.f) {
                int slot = j >> 6, c = j & 63;
                atomicAdd(&g_pool[(b0blk + slot) * 128 + pooloff + c], v);
            }
        }
        if (docnt && t < NSLOT && scnt[t] > 0)
            atomicAdd(&g_cnt[b0blk + t], scnt[t]);
    }
}

// ---------------- aggregation: one warp per node, CSR gather, no atomics -----
// T[node] = relu(U[node] + sum_e w_e * U[src_e] + bias)   (bias per-column)
__global__ void __launch_bounds__(256) agg_kernel(
    const float* __restrict__ U, const float* __restrict__ bias,
    float* __restrict__ T)
{
    int w = (blockIdx.x * blockDim.x + threadIdx.x) >> 5;
    int lane = threadIdx.x & 31;
    if (w >= NN) return;
    int s  = g_off[w];
    int dg = g_deg[w];
    float a0 = 0.f, a1 = 0.f;
    int e = 0;
    for (; e + 4 <= dg; e += 4) {
        uint2 c0 = g_csr[s + e + 0];
        uint2 c1 = g_csr[s + e + 1];
        uint2 c2 = g_csr[s + e + 2];
        uint2 c3 = g_csr[s + e + 3];
        float2 v0 = *(const float2*)(U + (size_t)c0.x * DD + 2 * lane);
        float2 v1 = *(const float2*)(U + (size_t)c1.x * DD + 2 * lane);
        float2 v2 = *(const float2*)(U + (size_t)c2.x * DD + 2 * lane);
        float2 v3 = *(const float2*)(U + (size_t)c3.x * DD + 2 * lane);
        float w0 = __uint_as_float(c0.y), w1 = __uint_as_float(c1.y);
        float w2 = __uint_as_float(c2.y), w3 = __uint_as_float(c3.y);
        a0 += w0 * v0.x; a1 += w0 * v0.y;
        a0 += w1 * v1.x; a1 += w1 * v1.y;
        a0 += w2 * v2.x; a1 += w2 * v2.y;
        a0 += w3 * v3.x; a1 += w3 * v3.y;
    }
    for (; e < dg; e++) {
        uint2 c = g_csr[s + e];
        float2 v = *(const float2*)(U + (size_t)c.x * DD + 2 * lane);
        float ww = __uint_as_float(c.y);
        a0 += ww * v.x; a1 += ww * v.y;
    }
    float2 u2 = *(const float2*)(U + (size_t)w * DD + 2 * lane);
    float b0 = bias[2 * lane], b1 = bias[2 * lane + 1];
    float2 o;
    o.x = fmaxf(u2.x + a0 + b0, 0.f);
    o.y = fmaxf(u2.y + a1 + b1, 0.f);
    *(float2*)(T + (size_t)w * DD + 2 * lane) = o;
}

// ---------------- finalize BN0 affine + fold into next-layer weights ---------
// h = sc0∘r + sh0 (per column). Layer-1 transform:
//   u = h@w1b = r@(diag(sc0)·w1b) + sh0@w1b  (constant folded into GEMM bias)
// Plain MLP bias b1b is added once per node AFTER aggregation.
__global__ void fin0_kernel(const float* __restrict__ gamma,
                            const float* __restrict__ beta,
                            const float* __restrict__ w1b)
{
    __shared__ float ssc[64], ssh[64];
    int t = threadIdx.x;
    if (t < 64) {
        float mean = g_colsum[t] * (1.f / NN);
        float var  = g_colsq[t] * (1.f / NN) - mean * mean;
        float sc = gamma[t] * rsqrtf(var + 1e-5f);
        float sh = beta[t] - mean * sc;
        g_sc0[t] = sc; g_sh0[t] = sh;
        ssc[t] = sc; ssh[t] = sh;
    }
    __syncthreads();
    #pragma unroll
    for (int j = 0; j < 16; j++) {
        int e = t + j * 256;           // 0..4095
        int k = e >> 6;
        g_w1bp[e] = ssc[k] * w1b[e];
    }
    if (t < 64) {
        float b = 0.f;                 // sh0 @ w1b only — b1b applied post-agg
        #pragma unroll 8
        for (int k = 0; k < 64; k++) b += ssh[k] * w1b[k * 64 + t];
        g_bias1b[t] = b;
    }
}

// ---------------- classifier head: one block per graph (inline BN1 affine) ---
// pool(BN(r)) = sc∘pool(r) + cnt·sh  (pools stored raw)
__global__ void head_kernel(const float* __restrict__ gm1, const float* __restrict__ bt1,
                            const float* __restrict__ wf,  const float* __restrict__ bf,
                            const float* __restrict__ wf1, const float* __restrict__ bf1,
                            const float* __restrict__ wf2, const float* __restrict__ bf2,
                            float* __restrict__ out)
{
    __shared__ float sg[128], a1[64], a2[64], lg[2];
    __shared__ float s1c[64], s1h[64];
    int g = blockIdx.x;
    int t = threadIdx.x;   // 64
    // inline fin1 (redundant per block; 128 loads + rsqrt)
    {
        float mean = g_colsum[64 + t] * (1.f / NN);
        float var  = g_colsq[64 + t] * (1.f / NN) - mean * mean;
        float sc = gm1[t] * rsqrtf(var + 1e-5f);
        s1c[t] = sc;
        s1h[t] = bt1[t] - mean * sc;
    }
    __syncthreads();
    float cnt = (float)g_cnt[g];
    sg[t]      = g_sc0[t] * g_pool[g * 128 + t]      + cnt * g_sh0[t];
    sg[t + 64] = s1c[t]   * g_pool[g * 128 + 64 + t] + cnt * s1h[t];
    __syncthreads();
    float acc = bf[t];
    #pragma unroll 4
    for (int k = 0; k < 128; k++) acc += sg[k] * wf[k * 64 + t];
    a1[t] = fmaxf(acc, 0.f);
    __syncthreads();
    acc = bf1[t];
    #pragma unroll 4
    for (int k = 0; k < 64; k++) acc += a1[k] * wf1[k * 64 + t];
    a2[t] = fmaxf(acc, 0.f);
    __syncthreads();
    if (t < 2) {
        float l = bf2[t];
        for (int k = 0; k < 64; k++) l += a2[k] * wf2[k * 2 + t];
        lg[t] = l;
    }
    __syncthreads();
    if (t == 0) {
        float l0 = lg[0], l1 = lg[1];
        float m = fmaxf(l0, l1);
        float lse = m + logf(expf(l0 - m) + expf(l1 - m));
        out[g * 2 + 0] = l0 - lse;
        out[g * 2 + 1] = l1 - lse;
    }
}

// ---------------- launch -----------------------------------------------------
extern "C" void kernel_launch(void* const* d_in, const int* in_sizes, int n_in,
                              void* d_out, int out_size)
{
    const float* x     = (const float*)d_in[0];
    const void*  ei    = d_in[1];
    const float* ew    = (const float*)d_in[2];
    const void*  batch = d_in[3];
    const float* w1a = (const float*)d_in[4];
    const float* b1a = (const float*)d_in[5];
    const float* w2a = (const float*)d_in[6];
    const float* b2a = (const float*)d_in[7];
    const float* gm0 = (const float*)d_in[8];
    const float* bt0 = (const float*)d_in[9];
    const float* w1b = (const float*)d_in[10];
    const float* b1b = (const float*)d_in[11];
    const float* w2b = (const float*)d_in[12];
    const float* b2b = (const float*)d_in[13];
    const float* gm1 = (const float*)d_in[14];
    const float* bt1 = (const float*)d_in[15];
    const float* wf  = (const float*)d_in[16];
    const float* bf  = (const float*)d_in[17];
    const float* wf1 = (const float*)d_in[18];
    const float* bf1 = (const float*)d_in[19];
    const float* wf2 = (const float*)d_in[20];
    const float* bf2 = (const float*)d_in[21];
    float* out = (float*)d_out;

    float *pu, *pt, *pr, *pcs, *pcq, *pw1bp, *pb1b;
    cudaGetSymbolAddress((void**)&pu,  g_u);
    cudaGetSymbolAddress((void**)&pt,  g_t);
    cudaGetSymbolAddress((void**)&pr,  g_r);
    cudaGetSymbolAddress((void**)&pcs, g_colsum);
    cudaGetSymbolAddress((void**)&pcq, g_colsq);
    cudaGetSymbolAddress((void**)&pw1bp, g_w1bp);
    cudaGetSymbolAddress((void**)&pb1b,  g_bias1b);

    int gemm_grid = (NN + 127) / 128;
    int agg_grid  = (NN * 32 + 255) / 256;

    // -- prep (5 launches; launch index 5 = the big FF GEMM for ncu -s 5)
    init_kernel<<<(NN + 255) / 256, 256>>>(ei, batch);                 // 0
    hist_kernel<<<(EE + 255) / 256, 256>>>(ei);                        // 1
    scanA_kernel<<<NBLK, SCAN_BLK>>>();                                // 2
    scanC_kernel<<<(NN + 255) / 256, 256>>>();                         // 3 (incl scanB)
    fill_kernel<<<(EE + 255) / 256, 256>>>(ei, ew);                    // 4

    // -- layer 0
    gemm_kernel<FF, false, false><<<gemm_grid, 256>>>(x, w1a, nullptr, pu,
        nullptr, nullptr, nullptr, 0, 0, NN);                          // 5 <- ncu
    agg_kernel<<<agg_grid, 256>>>(pu, b1a, pt);                        // 6
    gemm_kernel<DD, true, true><<<gemm_grid, 256>>>(pt, w2a, b2a, pr,
        pcs, pcq, batch, 0, 1, NN);                                    // 7 (+pool0)
    fin0_kernel<<<1, 256>>>(gm0, bt0, w1b);                            // 8

    // -- layer 1 (BN folded into w1bp; sh0@w1b inside GEMM bias; b1b post-agg)
    gemm_kernel<DD, false, false><<<gemm_grid, 256>>>(pr, pw1bp, pb1b, pu,
        nullptr, nullptr, nullptr, 0, 0, NN);                          // 9
    agg_kernel<<<agg_grid, 256>>>(pu, b1b, pt);                        // 10
    gemm_kernel<DD, true, true><<<gemm_grid, 256>>>(pt, w2b, b2b, pr,
        pcs + DD, pcq + DD, batch, DD, 0, NN);                         // 11 (+pool1)

    // -- head (inline BN1 affine)
    head_kernel<<<GG, 64>>>(gm1, bt1, wf, bf, wf1, bf1, wf2, bf2, out); // 12
}